// round 5
// baseline (speedup 1.0000x reference)
#include <cuda_runtime.h>
#include <cuda_bf16.h>
#include <math.h>
#include <stdint.h>

// Problem constants
#define LL 13
#define HH 48
#define WW 96
#define DD 512
#define TT (LL*HH*WW)        // 59904 tokens
#define NHEAD 16
#define HD 32

// GEMM tile config
#define BM 128
#define BN 256
#define BK 16
#define NSTAGE 3
#define AS_STRIDE 20          // 128 rows x 20
#define BS_STRIDE 264         // 16 rows x 264 (264 mod 32 == 8 -> conflict-free)
#define AS_ELEMS (BM * AS_STRIDE)           // 2560
#define BS_ELEMS (BK * BS_STRIDE)           // 4224
#define SMEM_BYTES ((NSTAGE * (AS_ELEMS + BS_ELEMS)) * 4)   // 81408

// Scratch (device globals; no cudaMalloc allowed)
__device__ float g_ln[(size_t)TT * DD];
__device__ float g_qkv[(size_t)TT * 3 * DD];
__device__ float g_att[(size_t)TT * DD];
__device__ float g_state[(size_t)TT * DD];
__device__ float g_sin_lat[HH * 16];
__device__ float g_cos_lat[HH * 16];
__device__ float g_sin_lon[WW * 16];
__device__ float g_cos_lon[WW * 16];

// ---------------------------------------------------------------------------
// Rotary sin/cos precompute. mode 0: lat axis (lon=0), mode 1: lon axis (lat=0)
// ---------------------------------------------------------------------------
__global__ void rotary_kernel(const float* __restrict__ grid, int S, int mode,
                              float* __restrict__ sout, float* __restrict__ cout)
{
    int idx = blockIdx.x * blockDim.x + threadIdx.x;
    if (idx >= S * 16) return;
    int s = idx >> 4;
    int f = idx & 15;
    const float PI = 3.14159265358979323846f;
    float lat, lon;
    if (mode == 0) { lat = grid[s]; lon = 0.f; }
    else           { lat = 0.f;     lon = grid[s]; }
    float two_pi = 2.f * PI;
    float r = fmodf(lon + PI, two_pi);
    if (r < 0.f) r += two_pi;
    float lonw = r - PI;
    float lo = -(PI * 0.5f) + 1e-6f;
    float hi =  (PI * 0.5f) - 1e-6f;
    float latc = fminf(fmaxf(lat, lo), hi);
    float invf = powf(10000.f, -(float)f / 16.f);
    float phase = (latc + lonw * cosf(latc)) * invf;
    sout[idx] = sinf(phase);
    cout[idx] = cosf(phase);
}

// ---------------------------------------------------------------------------
// LayerNorm over D=512 per token. 128 threads/block, one block per token.
// ---------------------------------------------------------------------------
__global__ void ln_kernel(const float* __restrict__ x, const float* __restrict__ g,
                          const float* __restrict__ b, float* __restrict__ out)
{
    __shared__ float red[8];
    int t = blockIdx.x;
    int tid = threadIdx.x;
    const float* row = x + (size_t)t * DD;
    float4 v = *(const float4*)(row + tid * 4);
    float s = v.x + v.y + v.z + v.w;
    float q = v.x*v.x + v.y*v.y + v.z*v.z + v.w*v.w;
    #pragma unroll
    for (int o = 16; o; o >>= 1) {
        s += __shfl_xor_sync(0xffffffffu, s, o);
        q += __shfl_xor_sync(0xffffffffu, q, o);
    }
    int lane = tid & 31, w = tid >> 5;
    if (lane == 0) { red[w] = s; red[4 + w] = q; }
    __syncthreads();
    if (tid == 0) {
        red[0] = red[0] + red[1] + red[2] + red[3];
        red[4] = red[4] + red[5] + red[6] + red[7];
    }
    __syncthreads();
    float mean = red[0] * (1.f / 512.f);
    float var  = red[4] * (1.f / 512.f) - mean * mean;
    float inv = rsqrtf(var + 1e-5f);
    float4 gv = *(const float4*)(g + tid * 4);
    float4 bv = *(const float4*)(b + tid * 4);
    float4 o;
    o.x = (v.x - mean) * inv * gv.x + bv.x;
    o.y = (v.y - mean) * inv * gv.y + bv.y;
    o.z = (v.z - mean) * inv * gv.z + bv.z;
    o.w = (v.w - mean) * inv * gv.w + bv.w;
    *(float4*)(out + (size_t)t * DD + tid * 4) = o;
}

// ---------------------------------------------------------------------------
// TF32 tensor-core GEMM: C[M,N] = A[M,K] @ B[K,N] + bias[N] (+ res[M,N])
// Block 128x256, 256 threads = 8 warps (2x4), warp tile 64x64.
// BK=16, cp.async 3-stage pipeline (wait_group 1), 1 __syncthreads/chunk.
// Dynamic smem, padded conflict-free layouts.
// ---------------------------------------------------------------------------
__device__ __forceinline__ void mma_tf32(float* d, const uint32_t* a, const uint32_t* b)
{
    asm volatile(
        "mma.sync.aligned.m16n8k8.row.col.f32.tf32.tf32.f32 "
        "{%0,%1,%2,%3}, {%4,%5,%6,%7}, {%8,%9}, {%0,%1,%2,%3};"
        : "+f"(d[0]), "+f"(d[1]), "+f"(d[2]), "+f"(d[3])
        : "r"(a[0]), "r"(a[1]), "r"(a[2]), "r"(a[3]), "r"(b[0]), "r"(b[1]));
}

__device__ __forceinline__ void cp_async16(uint32_t dst, const void* src)
{
    asm volatile("cp.async.cg.shared.global [%0], [%1], 16;\n" :: "r"(dst), "l"(src));
}

__device__ __forceinline__ void cp_commit()
{
    asm volatile("cp.async.commit_group;\n" ::: "memory");
}

__device__ __forceinline__ void cp_wait1()
{
    asm volatile("cp.async.wait_group 1;\n" ::: "memory");
}

// Issue one K-chunk's global->shared loads into pipeline stage `st`.
__device__ __forceinline__ void gemm_issue_chunk(
    const float* __restrict__ A, const float* __restrict__ B,
    int N, int K, int m0, int n0,
    int ar, int ac, int br, int bc,
    uint32_t as_base, uint32_t bs_base,
    int chunk, int st)
{
    int k0 = chunk * BK;
    #pragma unroll
    for (int i = 0; i < 2; i++) {
        uint32_t dst = as_base + (uint32_t)(((st * BM + ar + 64 * i) * AS_STRIDE + ac) * 4);
        cp_async16(dst, A + (size_t)(m0 + ar + 64 * i) * K + k0 + ac);
    }
    #pragma unroll
    for (int i = 0; i < 4; i++) {
        uint32_t dst = bs_base + (uint32_t)(((st * BK + br + 4 * i) * BS_STRIDE + bc) * 4);
        cp_async16(dst, B + (size_t)(k0 + br + 4 * i) * N + n0 + bc);
    }
    cp_commit();
}

extern __shared__ float smem_dyn[];

__global__ __launch_bounds__(256) void gemm_tc_kernel(
    const float* __restrict__ A, const float* __restrict__ B,
    const float* __restrict__ bias, const float* __restrict__ res,
    float* __restrict__ C, int M, int N, int K)
{
    float* As = smem_dyn;                        // [NSTAGE][BM][AS_STRIDE]
    float* Bs = smem_dyn + NSTAGE * AS_ELEMS;    // [NSTAGE][BK][BS_STRIDE]

    int tid  = threadIdx.x;
    int lane = tid & 31;
    int warp = tid >> 5;
    int wm   = warp >> 2;     // 0..1 -> 64 rows
    int wn   = warp & 3;      // 0..3 -> 64 cols
    int r    = lane >> 2;     // 0..7
    int c    = lane & 3;      // 0..3

    int m0 = blockIdx.y * BM;
    int n0 = blockIdx.x * BN;

    // Global->shared load mapping
    int ar = tid >> 2;             // 0..63 (A rows, +64*i)
    int ac = (tid & 3) * 4;        // 0,4,8,12
    int br = tid >> 6;             // 0..3  (B k-rows, +4*i)
    int bc = (tid & 63) * 4;       // B col 0..252

    uint32_t as_base = (uint32_t)__cvta_generic_to_shared(As);
    uint32_t bs_base = (uint32_t)__cvta_generic_to_shared(Bs);

    float acc[4][8][4];
    #pragma unroll
    for (int i = 0; i < 4; i++)
        #pragma unroll
        for (int j = 0; j < 8; j++)
            #pragma unroll
            for (int e = 0; e < 4; e++) acc[i][j][e] = 0.f;

    const int NCHUNK = K / BK;

    gemm_issue_chunk(A, B, N, K, m0, n0, ar, ac, br, bc, as_base, bs_base, 0, 0);
    gemm_issue_chunk(A, B, N, K, m0, n0, ar, ac, br, bc, as_base, bs_base, 1, 1);

    for (int chunk = 0; chunk < NCHUNK; chunk++) {
        int st = chunk % NSTAGE;
        cp_wait1();            // oldest outstanding group (this chunk) done
        __syncthreads();       // also protects buffer reuse before next issue

        if (chunk + 2 < NCHUNK)
            gemm_issue_chunk(A, B, N, K, m0, n0, ar, ac, br, bc,
                             as_base, bs_base, chunk + 2, (chunk + 2) % NSTAGE);

        const float* Asb = As + st * AS_ELEMS;
        const float* Bsb = Bs + st * BS_ELEMS;

        #pragma unroll
        for (int ks = 0; ks < 2; ks++) {
            int kb = ks * 8;
            uint32_t afrag[4][4];
            #pragma unroll
            for (int i = 0; i < 4; i++) {
                int row = wm * 64 + i * 16 + r;
                afrag[i][0] = __float_as_uint(Asb[row * AS_STRIDE + kb + c]);
                afrag[i][1] = __float_as_uint(Asb[(row + 8) * AS_STRIDE + kb + c]);
                afrag[i][2] = __float_as_uint(Asb[row * AS_STRIDE + kb + c + 4]);
                afrag[i][3] = __float_as_uint(Asb[(row + 8) * AS_STRIDE + kb + c + 4]);
            }
            uint32_t bfrag[8][2];
            #pragma unroll
            for (int j = 0; j < 8; j++) {
                int col = wn * 64 + j * 8 + r;
                bfrag[j][0] = __float_as_uint(Bsb[(kb + c) * BS_STRIDE + col]);
                bfrag[j][1] = __float_as_uint(Bsb[(kb + c + 4) * BS_STRIDE + col]);
            }
            #pragma unroll
            for (int i = 0; i < 4; i++)
                #pragma unroll
                for (int j = 0; j < 8; j++)
                    mma_tf32(acc[i][j], afrag[i], bfrag[j]);
        }
    }

    // Epilogue: bias + optional residual
    #pragma unroll
    for (int i = 0; i < 4; i++) {
        int row0 = m0 + wm * 64 + i * 16 + r;
        #pragma unroll
        for (int j = 0; j < 8; j++) {
            int col = n0 + wn * 64 + j * 8 + 2 * c;
            float bv0 = bias[col];
            float bv1 = bias[col + 1];
            size_t idx0 = (size_t)row0 * N + col;
            size_t idx1 = (size_t)(row0 + 8) * N + col;
            float2 o0, o1;
            o0.x = acc[i][j][0] + bv0; o0.y = acc[i][j][1] + bv1;
            o1.x = acc[i][j][2] + bv0; o1.y = acc[i][j][3] + bv1;
            if (res) {
                const float2 r0 = *(const float2*)(res + idx0);
                const float2 r1 = *(const float2*)(res + idx1);
                o0.x += r0.x; o0.y += r0.y;
                o1.x += r1.x; o1.y += r1.y;
            }
            *(float2*)(C + idx0) = o0;
            *(float2*)(C + idx1) = o1;
        }
    }
}

// ---------------------------------------------------------------------------
// Attention per (sequence n, head h). flat(n,s) = cd*(n/d0) + cm*(n%d0) + cs*s
// rsin/rcos: [S][16] rotary tables (nullptr -> no rotary, lev axis).
// ---------------------------------------------------------------------------
__global__ __launch_bounds__(128) void attn_kernel(
    const float* __restrict__ qkv, float* __restrict__ att,
    const float* __restrict__ rsin, const float* __restrict__ rcos,
    int S, int d0, int cd, int cm, int cs)
{
    __shared__ float k_s[96][33];
    __shared__ float v_s[96][33];
    __shared__ float probs[4][96];

    int n = blockIdx.x;
    int h = blockIdx.y;
    int tid = threadIdx.x;
    int lane = tid & 31;
    int warp = tid >> 5;

    int nb = cd * (n / d0) + cm * (n % d0);
    int qoff = h * HD;
    int koff = DD + h * HD;
    int voff = 2 * DD + h * HD;

    for (int idx = tid; idx < S * 32; idx += 128) {
        int j = idx >> 5;
        int d = idx & 31;
        size_t rowbase = (size_t)(nb + cs * j) * (3 * DD);
        float kv;
        if (rsin) {
            int i = d & 15;
            float sn = rsin[j * 16 + i], cs_ = rcos[j * 16 + i];
            float x1 = qkv[rowbase + koff + 2 * i];
            float x2 = qkv[rowbase + koff + 2 * i + 1];
            kv = (d < 16) ? (x1 * cs_ - x2 * sn) : (x1 * sn + x2 * cs_);
        } else {
            kv = qkv[rowbase + koff + d];
        }
        k_s[j][d] = kv;
        v_s[j][d] = qkv[rowbase + voff + d];
    }
    __syncthreads();

    const float scale = 0.17677669529663687f; // 1/sqrt(32)

    for (int sq = warp; sq < S; sq += 4) {
        size_t qrow = (size_t)(nb + cs * sq) * (3 * DD) + qoff;
        float q[32];
        if (rsin) {
            #pragma unroll
            for (int i = 0; i < 16; i++) {
                float sn = rsin[sq * 16 + i], cs_ = rcos[sq * 16 + i];
                float x1 = qkv[qrow + 2 * i];
                float x2 = qkv[qrow + 2 * i + 1];
                q[i]      = x1 * cs_ - x2 * sn;
                q[16 + i] = x1 * sn + x2 * cs_;
            }
        } else {
            #pragma unroll
            for (int i = 0; i < 32; i++) q[i] = qkv[qrow + i];
        }

        float sc[3];
        float mx = -1e30f;
        #pragma unroll
        for (int kb = 0; kb < 3; kb++) {
            int j = lane + kb * 32;
            float a = 0.f;
            if (j < S) {
                #pragma unroll
                for (int d = 0; d < 32; d++) a += q[d] * k_s[j][d];
                a *= scale;
                mx = fmaxf(mx, a);
            }
            sc[kb] = a;
        }
        #pragma unroll
        for (int o = 16; o; o >>= 1) mx = fmaxf(mx, __shfl_xor_sync(0xffffffffu, mx, o));

        float sum = 0.f;
        #pragma unroll
        for (int kb = 0; kb < 3; kb++) {
            int j = lane + kb * 32;
            if (j < S) {
                float e = expf(sc[kb] - mx);
                probs[warp][j] = e;
                sum += e;
            }
        }
        #pragma unroll
        for (int o = 16; o; o >>= 1) sum += __shfl_xor_sync(0xffffffffu, sum, o);
        float rinv = 1.f / sum;

        __syncwarp();
        float o = 0.f;
        for (int j = 0; j < S; j++) o += probs[warp][j] * v_s[j][lane];
        o *= rinv;
        att[(size_t)(nb + cs * sq) * DD + h * HD + lane] = o;
        __syncwarp();
    }
}

// ---------------------------------------------------------------------------
// Host launcher
// ---------------------------------------------------------------------------
extern "C" void kernel_launch(void* const* d_in, const int* in_sizes, int n_in,
                              void* d_out, int out_size)
{
    const float* x         = (const float*)d_in[0];
    const float* lat_grid  = (const float*)d_in[1];
    const float* lon_grid  = (const float*)d_in[2];
    const float* lat_qkv_w = (const float*)d_in[3];
    const float* lat_qkv_b = (const float*)d_in[4];
    const float* lon_qkv_w = (const float*)d_in[5];
    const float* lon_qkv_b = (const float*)d_in[6];
    const float* lev_qkv_w = (const float*)d_in[7];
    const float* lev_qkv_b = (const float*)d_in[8];
    const float* proj_w    = (const float*)d_in[9];
    const float* proj_b    = (const float*)d_in[10];
    const float* g_lat     = (const float*)d_in[11];
    const float* b_lat     = (const float*)d_in[12];
    const float* g_lon     = (const float*)d_in[13];
    const float* b_lon     = (const float*)d_in[14];
    const float* g_lev     = (const float*)d_in[15];
    const float* b_lev     = (const float*)d_in[16];
    float* out = (float*)d_out;

    float *ln, *qkv, *attb, *state, *slat, *clat, *slon, *clon;
    cudaGetSymbolAddress((void**)&ln,    g_ln);
    cudaGetSymbolAddress((void**)&qkv,   g_qkv);
    cudaGetSymbolAddress((void**)&attb,  g_att);
    cudaGetSymbolAddress((void**)&state, g_state);
    cudaGetSymbolAddress((void**)&slat,  g_sin_lat);
    cudaGetSymbolAddress((void**)&clat,  g_cos_lat);
    cudaGetSymbolAddress((void**)&slon,  g_sin_lon);
    cudaGetSymbolAddress((void**)&clon,  g_cos_lon);

    static int smem_set = 0;
    if (!smem_set) {
        cudaFuncSetAttribute(gemm_tc_kernel,
                             cudaFuncAttributeMaxDynamicSharedMemorySize, SMEM_BYTES);
        smem_set = 1;
    }

    rotary_kernel<<<(HH * 16 + 127) / 128, 128>>>(lat_grid, HH, 0, slat, clat);
    rotary_kernel<<<(WW * 16 + 127) / 128, 128>>>(lon_grid, WW, 1, slon, clon);

    dim3 gq(3 * DD / BN, TT / BM);   // QKV gemm grid (6, 468)
    dim3 gp(DD / BN, TT / BM);       // proj gemm grid (2, 468)

    // ---- lat block (seq = H, n over (l,w)) ----
    ln_kernel<<<TT, 128>>>(x, g_lat, b_lat, ln);
    gemm_tc_kernel<<<gq, 256, SMEM_BYTES>>>(ln, lat_qkv_w, lat_qkv_b, nullptr, qkv, TT, 3 * DD, DD);
    attn_kernel<<<dim3(LL * WW, NHEAD), 128>>>(qkv, attb, slat, clat,
                                               HH, WW, HH * WW, 1, WW);
    gemm_tc_kernel<<<gp, 256, SMEM_BYTES>>>(attb, proj_w, proj_b, x, state, TT, DD, DD);

    // ---- lon block (seq = W, n over (l,h)) ----
    ln_kernel<<<TT, 128>>>(state, g_lon, b_lon, ln);
    gemm_tc_kernel<<<gq, 256, SMEM_BYTES>>>(ln, lon_qkv_w, lon_qkv_b, nullptr, qkv, TT, 3 * DD, DD);
    attn_kernel<<<dim3(LL * HH, NHEAD), 128>>>(qkv, attb, slon, clon,
                                               WW, 1, WW, 0, 1);
    gemm_tc_kernel<<<gp, 256, SMEM_BYTES>>>(attb, proj_w, proj_b, state, state, TT, DD, DD);

    // ---- lev block (seq = L, n over (h,w), no rotary) ----
    ln_kernel<<<TT, 128>>>(state, g_lev, b_lev, ln);
    gemm_tc_kernel<<<gq, 256, SMEM_BYTES>>>(ln, lev_qkv_w, lev_qkv_b, nullptr, qkv, TT, 3 * DD, DD);
    attn_kernel<<<dim3(HH * WW, NHEAD), 128>>>(qkv, attb, nullptr, nullptr,
                                               LL, 1, 1, 0, HH * WW);
    gemm_tc_kernel<<<gp, 256, SMEM_BYTES>>>(attb, proj_w, proj_b, state, out, TT, DD, DD);
}

// round 6
// speedup vs baseline: 1.5445x; 1.5445x over previous
#include <cuda_runtime.h>
#include <cuda_bf16.h>
#include <math.h>
#include <stdint.h>

// Problem constants
#define LL 13
#define HH 48
#define WW 96
#define DD 512
#define TT (LL*HH*WW)        // 59904 tokens
#define NHEAD 16
#define HD 32

// Scratch (device globals; no cudaMalloc allowed)
__device__ float g_ln[(size_t)TT * DD];
__device__ float g_qkv[(size_t)TT * 3 * DD];
__device__ float g_att[(size_t)TT * DD];
__device__ float g_state[(size_t)TT * DD];
__device__ float g_sin_lat[HH * 16];
__device__ float g_cos_lat[HH * 16];
__device__ float g_sin_lon[WW * 16];
__device__ float g_cos_lon[WW * 16];

// ---------------------------------------------------------------------------
// Rotary sin/cos precompute. mode 0: lat axis (lon=0), mode 1: lon axis (lat=0)
// ---------------------------------------------------------------------------
__global__ void rotary_kernel(const float* __restrict__ grid, int S, int mode,
                              float* __restrict__ sout, float* __restrict__ cout)
{
    int idx = blockIdx.x * blockDim.x + threadIdx.x;
    if (idx >= S * 16) return;
    int s = idx >> 4;
    int f = idx & 15;
    const float PI = 3.14159265358979323846f;
    float lat, lon;
    if (mode == 0) { lat = grid[s]; lon = 0.f; }
    else           { lat = 0.f;     lon = grid[s]; }
    float two_pi = 2.f * PI;
    float r = fmodf(lon + PI, two_pi);
    if (r < 0.f) r += two_pi;
    float lonw = r - PI;
    float lo = -(PI * 0.5f) + 1e-6f;
    float hi =  (PI * 0.5f) - 1e-6f;
    float latc = fminf(fmaxf(lat, lo), hi);
    float invf = powf(10000.f, -(float)f / 16.f);
    float phase = (latc + lonw * cosf(latc)) * invf;
    sout[idx] = sinf(phase);
    cout[idx] = cosf(phase);
}

// ---------------------------------------------------------------------------
// LayerNorm over D=512 per token. 128 threads/block, one block per token.
// ---------------------------------------------------------------------------
__global__ void ln_kernel(const float* __restrict__ x, const float* __restrict__ g,
                          const float* __restrict__ b, float* __restrict__ out)
{
    __shared__ float red[8];
    int t = blockIdx.x;
    int tid = threadIdx.x;
    const float* row = x + (size_t)t * DD;
    float4 v = *(const float4*)(row + tid * 4);
    float s = v.x + v.y + v.z + v.w;
    float q = v.x*v.x + v.y*v.y + v.z*v.z + v.w*v.w;
    #pragma unroll
    for (int o = 16; o; o >>= 1) {
        s += __shfl_xor_sync(0xffffffffu, s, o);
        q += __shfl_xor_sync(0xffffffffu, q, o);
    }
    int lane = tid & 31, w = tid >> 5;
    if (lane == 0) { red[w] = s; red[4 + w] = q; }
    __syncthreads();
    if (tid == 0) {
        red[0] = red[0] + red[1] + red[2] + red[3];
        red[4] = red[4] + red[5] + red[6] + red[7];
    }
    __syncthreads();
    float mean = red[0] * (1.f / 512.f);
    float var  = red[4] * (1.f / 512.f) - mean * mean;
    float inv = rsqrtf(var + 1e-5f);
    float4 gv = *(const float4*)(g + tid * 4);
    float4 bv = *(const float4*)(b + tid * 4);
    float4 o;
    o.x = (v.x - mean) * inv * gv.x + bv.x;
    o.y = (v.y - mean) * inv * gv.y + bv.y;
    o.z = (v.z - mean) * inv * gv.z + bv.z;
    o.w = (v.w - mean) * inv * gv.w + bv.w;
    *(float4*)(out + (size_t)t * DD + tid * 4) = o;
}

// ---------------------------------------------------------------------------
// MMA wrappers
// ---------------------------------------------------------------------------
__device__ __forceinline__ void mma_tf32(float* d, const uint32_t* a, const uint32_t* b)
{
    asm volatile(
        "mma.sync.aligned.m16n8k8.row.col.f32.tf32.tf32.f32 "
        "{%0,%1,%2,%3}, {%4,%5,%6,%7}, {%8,%9}, {%0,%1,%2,%3};"
        : "+f"(d[0]), "+f"(d[1]), "+f"(d[2]), "+f"(d[3])
        : "r"(a[0]), "r"(a[1]), "r"(a[2]), "r"(a[3]), "r"(b[0]), "r"(b[1]));
}

__device__ __forceinline__ void mma_bf16(float* d, const uint32_t* a, const uint32_t* b)
{
    asm volatile(
        "mma.sync.aligned.m16n8k16.row.col.f32.bf16.bf16.f32 "
        "{%0,%1,%2,%3}, {%4,%5,%6,%7}, {%8,%9}, {%0,%1,%2,%3};"
        : "+f"(d[0]), "+f"(d[1]), "+f"(d[2]), "+f"(d[3])
        : "r"(a[0]), "r"(a[1]), "r"(a[2]), "r"(a[3]), "r"(b[0]), "r"(b[1]));
}

__device__ __forceinline__ uint32_t pack_bf2(float lo, float hi)
{
    __nv_bfloat162 t = __floats2bfloat162_rn(lo, hi);
    return *(uint32_t*)&t;
}

__device__ __forceinline__ void cp_async16(uint32_t dst, const void* src)
{
    asm volatile("cp.async.cg.shared.global [%0], [%1], 16;\n" :: "r"(dst), "l"(src));
}
__device__ __forceinline__ void cp_commit()
{
    asm volatile("cp.async.commit_group;\n" ::: "memory");
}
__device__ __forceinline__ void cp_wait0()
{
    asm volatile("cp.async.wait_group 0;\n" ::: "memory");
}

// ---------------------------------------------------------------------------
// TF32 tensor-core GEMM (round-4 config): C = A@B + bias (+ res)
// Block 128x128, 128 threads = 4 warps (2x2), warp tile 64x64.
// BK=16, cp.async 2-stage double buffer.
// ---------------------------------------------------------------------------
__device__ __forceinline__ void gemm_issue_chunk(
    const float* __restrict__ A, const float* __restrict__ B,
    int N, int K, int m0, int n0,
    int ar, int ac, int br, int bc,
    uint32_t as_base, uint32_t bs_base,
    int chunk, int buf)
{
    int k0 = chunk * 16;
    #pragma unroll
    for (int i = 0; i < 4; i++) {
        uint32_t dst = as_base + (uint32_t)(((buf * 128 + ar + 32 * i) * 20 + ac) * 4);
        cp_async16(dst, A + (size_t)(m0 + ar + 32 * i) * K + k0 + ac);
    }
    #pragma unroll
    for (int i = 0; i < 4; i++) {
        uint32_t dst = bs_base + (uint32_t)(((buf * 16 + br + 4 * i) * 136 + bc) * 4);
        cp_async16(dst, B + (size_t)(k0 + br + 4 * i) * N + n0 + bc);
    }
    cp_commit();
}

__global__ __launch_bounds__(128) void gemm_tc_kernel(
    const float* __restrict__ A, const float* __restrict__ B,
    const float* __restrict__ bias, const float* __restrict__ res,
    float* __restrict__ C, int M, int N, int K)
{
    __shared__ float As[2][128][20];
    __shared__ float Bs[2][16][136];

    int tid  = threadIdx.x;
    int lane = tid & 31;
    int warp = tid >> 5;
    int wm   = warp >> 1;
    int wn   = warp & 1;
    int r    = lane >> 2;
    int c    = lane & 3;

    int m0 = blockIdx.y * 128;
    int n0 = blockIdx.x * 128;

    int ar = tid >> 2;
    int ac = (tid & 3) * 4;
    int br = tid >> 5;
    int bc = (tid & 31) * 4;

    uint32_t as_base = (uint32_t)__cvta_generic_to_shared(&As[0][0][0]);
    uint32_t bs_base = (uint32_t)__cvta_generic_to_shared(&Bs[0][0][0]);

    float acc[4][8][4];
    #pragma unroll
    for (int i = 0; i < 4; i++)
        #pragma unroll
        for (int j = 0; j < 8; j++)
            #pragma unroll
            for (int e = 0; e < 4; e++) acc[i][j][e] = 0.f;

    const int NCHUNK = K / 16;

    gemm_issue_chunk(A, B, N, K, m0, n0, ar, ac, br, bc, as_base, bs_base, 0, 0);

    for (int chunk = 0; chunk < NCHUNK; chunk++) {
        int buf = chunk & 1;
        cp_wait0();
        __syncthreads();

        if (chunk + 1 < NCHUNK)
            gemm_issue_chunk(A, B, N, K, m0, n0, ar, ac, br, bc,
                             as_base, bs_base, chunk + 1, buf ^ 1);

        #pragma unroll
        for (int ks = 0; ks < 2; ks++) {
            int kb = ks * 8;
            uint32_t afrag[4][4];
            #pragma unroll
            for (int i = 0; i < 4; i++) {
                int row = wm * 64 + i * 16 + r;
                afrag[i][0] = __float_as_uint(As[buf][row][kb + c]);
                afrag[i][1] = __float_as_uint(As[buf][row + 8][kb + c]);
                afrag[i][2] = __float_as_uint(As[buf][row][kb + c + 4]);
                afrag[i][3] = __float_as_uint(As[buf][row + 8][kb + c + 4]);
            }
            uint32_t bfrag[8][2];
            #pragma unroll
            for (int j = 0; j < 8; j++) {
                int col = wn * 64 + j * 8 + r;
                bfrag[j][0] = __float_as_uint(Bs[buf][kb + c][col]);
                bfrag[j][1] = __float_as_uint(Bs[buf][kb + c + 4][col]);
            }
            #pragma unroll
            for (int i = 0; i < 4; i++)
                #pragma unroll
                for (int j = 0; j < 8; j++)
                    mma_tf32(acc[i][j], afrag[i], bfrag[j]);
        }
        __syncthreads();
    }

    #pragma unroll
    for (int i = 0; i < 4; i++) {
        int row0 = m0 + wm * 64 + i * 16 + r;
        #pragma unroll
        for (int j = 0; j < 8; j++) {
            int col = n0 + wn * 64 + j * 8 + 2 * c;
            float bv0 = bias[col];
            float bv1 = bias[col + 1];
            size_t idx0 = (size_t)row0 * N + col;
            size_t idx1 = (size_t)(row0 + 8) * N + col;
            float2 o0, o1;
            o0.x = acc[i][j][0] + bv0; o0.y = acc[i][j][1] + bv1;
            o1.x = acc[i][j][2] + bv0; o1.y = acc[i][j][3] + bv1;
            if (res) {
                const float2 r0 = *(const float2*)(res + idx0);
                const float2 r1 = *(const float2*)(res + idx1);
                o0.x += r0.x; o0.y += r0.y;
                o1.x += r1.x; o1.y += r1.y;
            }
            *(float2*)(C + idx0) = o0;
            *(float2*)(C + idx1) = o1;
        }
    }
}

// ---------------------------------------------------------------------------
// Tensor-core attention per (n, h). flat(n,s) = cd*(n/d0) + cm*(n%d0) + cs*s
// Scores via tf32 mma (Q staged rotated+scaled, K^T staged), softmax in
// registers (whole S fits), P@V via bf16 mma (acc->afrag is register-local).
// 128 threads = 4 warps; warps take 16-row q-tiles round robin.
// ---------------------------------------------------------------------------
template<int S>
__global__ __launch_bounds__(128) void attn_mma_kernel(
    const float* __restrict__ qkv, float* __restrict__ att,
    const float* __restrict__ rsin, const float* __restrict__ rcos,
    int d0, int cd, int cm, int cs)
{
    constexpr int NT   = (S + 7) / 8;      // 8-wide score col tiles
    constexpr int QT   = (S + 15) / 16;    // 16-row q tiles
    constexpr int KT2  = NT / 2;           // 16-wide PV k steps (NT even for 48/96/13->2)
    constexpr int NT8  = NT * 8;
    constexpr int KSTR = NT8 + ((8 - (NT8 % 32) + 32) % 32);  // stride %32 == 8
    constexpr int QROWS = QT * 16;

    __shared__ float    Qs[QROWS][36];     // stride 36: banks 4r+c conflict-free
    __shared__ float    Kt[32][KSTR];      // [d][j]
    __shared__ uint32_t Vp[NT * 4][40];    // bf16 pairs (j, j+1) per word; stride%32==8

    int n = blockIdx.x;
    int h = blockIdx.y;
    int tid = threadIdx.x;
    int lane = tid & 31;
    int warp = tid >> 5;
    int r = lane >> 2;
    int c = lane & 3;

    int nb = cd * (n / d0) + cm * (n % d0);
    int qoff = h * HD;
    int koff = DD + h * HD;
    int voff = 2 * DD + h * HD;
    const float scale = 0.17677669529663687f; // 1/sqrt(32)

    // ---- Stage Q (rotated + pre-scaled; zero-padded rows) ----
    for (int idx = tid; idx < QROWS * 32; idx += 128) {
        int j = idx >> 5, d = idx & 31;
        float val = 0.f;
        if (j < S) {
            size_t rowb = (size_t)(nb + cs * j) * (3 * DD);
            if (rsin) {
                int i = d & 15;
                float sn = rsin[j * 16 + i], co = rcos[j * 16 + i];
                float x1 = qkv[rowb + qoff + 2 * i];
                float x2 = qkv[rowb + qoff + 2 * i + 1];
                val = (d < 16) ? (x1 * co - x2 * sn) : (x1 * sn + x2 * co);
            } else {
                val = qkv[rowb + qoff + d];
            }
            val *= scale;
        }
        Qs[j][d] = val;
    }
    // ---- Stage K^T (rotated; zero-padded cols) ----
    for (int idx = tid; idx < NT8 * 32; idx += 128) {
        int j = idx >> 5, d = idx & 31;
        float val = 0.f;
        if (j < S) {
            size_t rowb = (size_t)(nb + cs * j) * (3 * DD);
            if (rsin) {
                int i = d & 15;
                float sn = rsin[j * 16 + i], co = rcos[j * 16 + i];
                float x1 = qkv[rowb + koff + 2 * i];
                float x2 = qkv[rowb + koff + 2 * i + 1];
                val = (d < 16) ? (x1 * co - x2 * sn) : (x1 * sn + x2 * co);
            } else {
                val = qkv[rowb + koff + d];
            }
        }
        Kt[d][j] = val;
    }
    // ---- Stage V as bf16 (j, j+1) pairs; zero-padded ----
    for (int idx = tid; idx < NT * 4 * 32; idx += 128) {
        int j2 = idx >> 5, d = idx & 31;
        int j0 = 2 * j2, j1 = 2 * j2 + 1;
        float v0 = (j0 < S) ? qkv[(size_t)(nb + cs * j0) * (3 * DD) + voff + d] : 0.f;
        float v1 = (j1 < S) ? qkv[(size_t)(nb + cs * j1) * (3 * DD) + voff + d] : 0.f;
        Vp[j2][d] = pack_bf2(v0, v1);
    }
    __syncthreads();

    for (int qt = warp; qt < QT; qt += 4) {
        int q0 = qt * 16;

        // Q fragments: 4 k-steps (k = kb*8 + {c, c+4})
        uint32_t aq[4][4];
        #pragma unroll
        for (int kb = 0; kb < 4; kb++) {
            aq[kb][0] = __float_as_uint(Qs[q0 + r][kb * 8 + c]);
            aq[kb][1] = __float_as_uint(Qs[q0 + 8 + r][kb * 8 + c]);
            aq[kb][2] = __float_as_uint(Qs[q0 + r][kb * 8 + c + 4]);
            aq[kb][3] = __float_as_uint(Qs[q0 + 8 + r][kb * 8 + c + 4]);
        }

        // Scores
        float sacc[NT][4];
        #pragma unroll
        for (int nt = 0; nt < NT; nt++)
            #pragma unroll
            for (int e = 0; e < 4; e++) sacc[nt][e] = 0.f;

        #pragma unroll
        for (int nt = 0; nt < NT; nt++) {
            #pragma unroll
            for (int kb = 0; kb < 4; kb++) {
                uint32_t bk[2];
                bk[0] = __float_as_uint(Kt[kb * 8 + c][nt * 8 + r]);
                bk[1] = __float_as_uint(Kt[kb * 8 + c + 4][nt * 8 + r]);
                mma_tf32(sacc[nt], aq[kb], bk);
            }
        }

        // Mask padded key columns
        #pragma unroll
        for (int nt = 0; nt < NT; nt++) {
            int col = nt * 8 + 2 * c;
            if (col >= S)     { sacc[nt][0] = -1e30f; sacc[nt][2] = -1e30f; }
            if (col + 1 >= S) { sacc[nt][1] = -1e30f; sacc[nt][3] = -1e30f; }
        }

        // Row max (rows r and r+8) via quad shuffles
        float m0 = -1e30f, m1 = -1e30f;
        #pragma unroll
        for (int nt = 0; nt < NT; nt++) {
            m0 = fmaxf(m0, fmaxf(sacc[nt][0], sacc[nt][1]));
            m1 = fmaxf(m1, fmaxf(sacc[nt][2], sacc[nt][3]));
        }
        m0 = fmaxf(m0, __shfl_xor_sync(0xffffffffu, m0, 1));
        m0 = fmaxf(m0, __shfl_xor_sync(0xffffffffu, m0, 2));
        m1 = fmaxf(m1, __shfl_xor_sync(0xffffffffu, m1, 1));
        m1 = fmaxf(m1, __shfl_xor_sync(0xffffffffu, m1, 2));

        // Exp + row sums
        float s0 = 0.f, s1 = 0.f;
        #pragma unroll
        for (int nt = 0; nt < NT; nt++) {
            sacc[nt][0] = __expf(sacc[nt][0] - m0);
            sacc[nt][1] = __expf(sacc[nt][1] - m0);
            sacc[nt][2] = __expf(sacc[nt][2] - m1);
            sacc[nt][3] = __expf(sacc[nt][3] - m1);
            s0 += sacc[nt][0] + sacc[nt][1];
            s1 += sacc[nt][2] + sacc[nt][3];
        }
        s0 += __shfl_xor_sync(0xffffffffu, s0, 1);
        s0 += __shfl_xor_sync(0xffffffffu, s0, 2);
        s1 += __shfl_xor_sync(0xffffffffu, s1, 1);
        s1 += __shfl_xor_sync(0xffffffffu, s1, 2);
        float rinv0 = 1.f / s0;
        float rinv1 = 1.f / s1;

        // P -> bf16 a-fragments (register-local: acc pairs (2c,2c+1) == afrag k pairs)
        uint32_t pa[KT2][4];
        #pragma unroll
        for (int kt = 0; kt < KT2; kt++) {
            int nt0 = 2 * kt, nt1 = 2 * kt + 1;
            pa[kt][0] = pack_bf2(sacc[nt0][0], sacc[nt0][1]);
            pa[kt][1] = pack_bf2(sacc[nt0][2], sacc[nt0][3]);
            pa[kt][2] = pack_bf2(sacc[nt1][0], sacc[nt1][1]);
            pa[kt][3] = pack_bf2(sacc[nt1][2], sacc[nt1][3]);
        }

        // P @ V
        float oacc[4][4];
        #pragma unroll
        for (int dt = 0; dt < 4; dt++)
            #pragma unroll
            for (int e = 0; e < 4; e++) oacc[dt][e] = 0.f;

        #pragma unroll
        for (int kt = 0; kt < KT2; kt++) {
            #pragma unroll
            for (int dt = 0; dt < 4; dt++) {
                uint32_t bv[2];
                bv[0] = Vp[8 * kt + c][dt * 8 + r];
                bv[1] = Vp[8 * kt + c + 4][dt * 8 + r];
                mma_bf16(oacc[dt], pa[kt], bv);
            }
        }

        // Epilogue: normalize + write
        int row0 = q0 + r;
        int row1 = q0 + 8 + r;
        #pragma unroll
        for (int dt = 0; dt < 4; dt++) {
            if (row0 < S) {
                float2 o = make_float2(oacc[dt][0] * rinv0, oacc[dt][1] * rinv0);
                *(float2*)&att[(size_t)(nb + cs * row0) * DD + h * HD + dt * 8 + 2 * c] = o;
            }
            if (row1 < S) {
                float2 o = make_float2(oacc[dt][2] * rinv1, oacc[dt][3] * rinv1);
                *(float2*)&att[(size_t)(nb + cs * row1) * DD + h * HD + dt * 8 + 2 * c] = o;
            }
        }
    }
}

// ---------------------------------------------------------------------------
// Host launcher
// ---------------------------------------------------------------------------
extern "C" void kernel_launch(void* const* d_in, const int* in_sizes, int n_in,
                              void* d_out, int out_size)
{
    const float* x         = (const float*)d_in[0];
    const float* lat_grid  = (const float*)d_in[1];
    const float* lon_grid  = (const float*)d_in[2];
    const float* lat_qkv_w = (const float*)d_in[3];
    const float* lat_qkv_b = (const float*)d_in[4];
    const float* lon_qkv_w = (const float*)d_in[5];
    const float* lon_qkv_b = (const float*)d_in[6];
    const float* lev_qkv_w = (const float*)d_in[7];
    const float* lev_qkv_b = (const float*)d_in[8];
    const float* proj_w    = (const float*)d_in[9];
    const float* proj_b    = (const float*)d_in[10];
    const float* g_lat     = (const float*)d_in[11];
    const float* b_lat     = (const float*)d_in[12];
    const float* g_lon     = (const float*)d_in[13];
    const float* b_lon     = (const float*)d_in[14];
    const float* g_lev     = (const float*)d_in[15];
    const float* b_lev     = (const float*)d_in[16];
    float* out = (float*)d_out;

    float *ln, *qkv, *attb, *state, *slat, *clat, *slon, *clon;
    cudaGetSymbolAddress((void**)&ln,    g_ln);
    cudaGetSymbolAddress((void**)&qkv,   g_qkv);
    cudaGetSymbolAddress((void**)&attb,  g_att);
    cudaGetSymbolAddress((void**)&state, g_state);
    cudaGetSymbolAddress((void**)&slat,  g_sin_lat);
    cudaGetSymbolAddress((void**)&clat,  g_cos_lat);
    cudaGetSymbolAddress((void**)&slon,  g_sin_lon);
    cudaGetSymbolAddress((void**)&clon,  g_cos_lon);

    rotary_kernel<<<(HH * 16 + 127) / 128, 128>>>(lat_grid, HH, 0, slat, clat);
    rotary_kernel<<<(WW * 16 + 127) / 128, 128>>>(lon_grid, WW, 1, slon, clon);

    dim3 gq(3 * DD / 128, TT / 128);   // QKV gemm grid (12, 468)
    dim3 gp(DD / 128, TT / 128);       // proj gemm grid (4, 468)

    // ---- lat block (seq = H, n over (l,w)) ----
    ln_kernel<<<TT, 128>>>(x, g_lat, b_lat, ln);
    gemm_tc_kernel<<<gq, 128>>>(ln, lat_qkv_w, lat_qkv_b, nullptr, qkv, TT, 3 * DD, DD);
    attn_mma_kernel<HH><<<dim3(LL * WW, NHEAD), 128>>>(qkv, attb, slat, clat,
                                                       WW, HH * WW, 1, WW);
    gemm_tc_kernel<<<gp, 128>>>(attb, proj_w, proj_b, x, state, TT, DD, DD);

    // ---- lon block (seq = W, n over (l,h)) ----
    ln_kernel<<<TT, 128>>>(state, g_lon, b_lon, ln);
    gemm_tc_kernel<<<gq, 128>>>(ln, lon_qkv_w, lon_qkv_b, nullptr, qkv, TT, 3 * DD, DD);
    attn_mma_kernel<WW><<<dim3(LL * HH, NHEAD), 128>>>(qkv, attb, slon, clon,
                                                       1, WW, 0, 1);
    gemm_tc_kernel<<<gp, 128>>>(attb, proj_w, proj_b, state, state, TT, DD, DD);

    // ---- lev block (seq = L, n over (h,w), no rotary) ----
    ln_kernel<<<TT, 128>>>(state, g_lev, b_lev, ln);
    gemm_tc_kernel<<<gq, 128>>>(ln, lev_qkv_w, lev_qkv_b, nullptr, qkv, TT, 3 * DD, DD);
    attn_mma_kernel<LL><<<dim3(HH * WW, NHEAD), 128>>>(qkv, attb, nullptr, nullptr,
                                                       1, 1, 0, HH * WW);
    gemm_tc_kernel<<<gp, 128>>>(attb, proj_w, proj_b, state, out, TT, DD, DD);
}

// round 8
// speedup vs baseline: 2.2907x; 1.4832x over previous
#include <cuda_runtime.h>
#include <cuda_bf16.h>
#include <cuda_fp16.h>
#include <math.h>
#include <stdint.h>

// Problem constants
#define LL 13
#define HH 48
#define WW 96
#define DD 512
#define TT (LL*HH*WW)        // 59904 tokens
#define NHEAD 16
#define HD 32

// Scratch (device globals; no cudaMalloc allowed)
__device__ __half g_lnh[(size_t)TT * DD];          // LN output (GEMM A), f16
__device__ float  g_qkv[(size_t)TT * 3 * DD];      // QKV output, fp32
__device__ __half g_atth[(size_t)TT * DD];         // attention output (proj A), f16
__device__ float  g_state[(size_t)TT * DD];        // residual stream, fp32
__device__ float  g_sin_lat[HH * 16];
__device__ float  g_cos_lat[HH * 16];
__device__ float  g_sin_lon[WW * 16];
__device__ float  g_cos_lon[WW * 16];
__device__ uint32_t g_wp_qkv[3][(DD / 2) * 3 * DD];  // packed f16 weights [K/2][N]
__device__ uint32_t g_wp_proj[(DD / 2) * DD];

// ---------------------------------------------------------------------------
// MMA wrappers
// ---------------------------------------------------------------------------
__device__ __forceinline__ void mma_f16(float* d, const uint32_t* a, const uint32_t* b)
{
    asm volatile(
        "mma.sync.aligned.m16n8k16.row.col.f32.f16.f16.f32 "
        "{%0,%1,%2,%3}, {%4,%5,%6,%7}, {%8,%9}, {%0,%1,%2,%3};"
        : "+f"(d[0]), "+f"(d[1]), "+f"(d[2]), "+f"(d[3])
        : "r"(a[0]), "r"(a[1]), "r"(a[2]), "r"(a[3]), "r"(b[0]), "r"(b[1]));
}

__device__ __forceinline__ void mma_tf32(float* d, const uint32_t* a, const uint32_t* b)
{
    asm volatile(
        "mma.sync.aligned.m16n8k8.row.col.f32.tf32.tf32.f32 "
        "{%0,%1,%2,%3}, {%4,%5,%6,%7}, {%8,%9}, {%0,%1,%2,%3};"
        : "+f"(d[0]), "+f"(d[1]), "+f"(d[2]), "+f"(d[3])
        : "r"(a[0]), "r"(a[1]), "r"(a[2]), "r"(a[3]), "r"(b[0]), "r"(b[1]));
}

__device__ __forceinline__ void mma_bf16(float* d, const uint32_t* a, const uint32_t* b)
{
    asm volatile(
        "mma.sync.aligned.m16n8k16.row.col.f32.bf16.bf16.f32 "
        "{%0,%1,%2,%3}, {%4,%5,%6,%7}, {%8,%9}, {%0,%1,%2,%3};"
        : "+f"(d[0]), "+f"(d[1]), "+f"(d[2]), "+f"(d[3])
        : "r"(a[0]), "r"(a[1]), "r"(a[2]), "r"(a[3]), "r"(b[0]), "r"(b[1]));
}

__device__ __forceinline__ uint32_t pack_bf2(float lo, float hi)
{
    __nv_bfloat162 t = __floats2bfloat162_rn(lo, hi);
    return *(uint32_t*)&t;
}
__device__ __forceinline__ uint32_t pack_h2(float lo, float hi)
{
    __half2 t = __floats2half2_rn(lo, hi);
    return *(uint32_t*)&t;
}

__device__ __forceinline__ void cp_async16(uint32_t dst, const void* src)
{
    asm volatile("cp.async.cg.shared.global [%0], [%1], 16;\n" :: "r"(dst), "l"(src));
}
__device__ __forceinline__ void cp_commit()
{
    asm volatile("cp.async.commit_group;\n" ::: "memory");
}
__device__ __forceinline__ void cp_wait0()
{
    asm volatile("cp.async.wait_group 0;\n" ::: "memory");
}

// ---------------------------------------------------------------------------
// Weight pack: W[K][N] fp32 -> out[k2][n] = half2(W[2k2][n], W[2k2+1][n])
// ---------------------------------------------------------------------------
__global__ void pack_w_kernel(const float* __restrict__ W, uint32_t* __restrict__ out,
                              int K, int N)
{
    int n  = blockIdx.x * 256 + threadIdx.x;
    int k2 = blockIdx.y;
    if (n < N)
        out[(size_t)k2 * N + n] =
            pack_h2(W[(size_t)(2 * k2) * N + n], W[(size_t)(2 * k2 + 1) * N + n]);
}

// ---------------------------------------------------------------------------
// Rotary sin/cos precompute. mode 0: lat axis (lon=0), mode 1: lon axis (lat=0)
// ---------------------------------------------------------------------------
__global__ void rotary_kernel(const float* __restrict__ grid, int S, int mode,
                              float* __restrict__ sout, float* __restrict__ cout)
{
    int idx = blockIdx.x * blockDim.x + threadIdx.x;
    if (idx >= S * 16) return;
    int s = idx >> 4;
    int f = idx & 15;
    const float PI = 3.14159265358979323846f;
    float lat, lon;
    if (mode == 0) { lat = grid[s]; lon = 0.f; }
    else           { lat = 0.f;     lon = grid[s]; }
    float two_pi = 2.f * PI;
    float r = fmodf(lon + PI, two_pi);
    if (r < 0.f) r += two_pi;
    float lonw = r - PI;
    float lo = -(PI * 0.5f) + 1e-6f;
    float hi =  (PI * 0.5f) - 1e-6f;
    float latc = fminf(fmaxf(lat, lo), hi);
    float invf = powf(10000.f, -(float)f / 16.f);
    float phase = (latc + lonw * cosf(latc)) * invf;
    sout[idx] = sinf(phase);
    cout[idx] = cosf(phase);
}

// ---------------------------------------------------------------------------
// LayerNorm over D=512 per token -> f16 output. 128 threads/block.
// ---------------------------------------------------------------------------
__global__ void ln_kernel(const float* __restrict__ x, const float* __restrict__ g,
                          const float* __restrict__ b, __half* __restrict__ out)
{
    __shared__ float red[8];
    int t = blockIdx.x;
    int tid = threadIdx.x;
    const float* row = x + (size_t)t * DD;
    float4 v = *(const float4*)(row + tid * 4);
    float s = v.x + v.y + v.z + v.w;
    float q = v.x*v.x + v.y*v.y + v.z*v.z + v.w*v.w;
    #pragma unroll
    for (int o = 16; o; o >>= 1) {
        s += __shfl_xor_sync(0xffffffffu, s, o);
        q += __shfl_xor_sync(0xffffffffu, q, o);
    }
    int lane = tid & 31, w = tid >> 5;
    if (lane == 0) { red[w] = s; red[4 + w] = q; }
    __syncthreads();
    if (tid == 0) {
        red[0] = red[0] + red[1] + red[2] + red[3];
        red[4] = red[4] + red[5] + red[6] + red[7];
    }
    __syncthreads();
    float mean = red[0] * (1.f / 512.f);
    float var  = red[4] * (1.f / 512.f) - mean * mean;
    float inv = rsqrtf(var + 1e-5f);
    float4 gv = *(const float4*)(g + tid * 4);
    float4 bv = *(const float4*)(b + tid * 4);
    uint2 o;
    o.x = pack_h2((v.x - mean) * inv * gv.x + bv.x, (v.y - mean) * inv * gv.y + bv.y);
    o.y = pack_h2((v.z - mean) * inv * gv.z + bv.z, (v.w - mean) * inv * gv.w + bv.w);
    *(uint2*)(out + (size_t)t * DD + tid * 4) = o;
}

// ---------------------------------------------------------------------------
// F16 tensor-core GEMM: C[M,N] = A[M,K] @ B[K,N] + bias[N] (+ res[M,N])
// A: f16 row-major. Bp: packed u32 [K/2][N], word = (B[2k2][n], B[2k2+1][n]).
// Block 128x128, 4 warps @64x64, BK=32 elems, 2-stage cp.async.
// Smem: Au32[2][128][20] (words, pad 20), Bu32[2][16][136].
// ---------------------------------------------------------------------------
__device__ __forceinline__ void gemm_issue_chunk(
    const __half* __restrict__ A, const uint32_t* __restrict__ Bp,
    int N, int K, int m0, int n0, int tid,
    uint32_t as_base, uint32_t bs_base,
    int chunk, int buf)
{
    int k0 = chunk * 32;
    // A: 128 rows x 64B (32 halves); 16B covers 8 halves (4 words)
    int arow = tid >> 2;           // 0..31 (+32*i)
    int aq   = tid & 3;            // word group 0..3
    #pragma unroll
    for (int i = 0; i < 4; i++) {
        int row = arow + 32 * i;
        uint32_t dst = as_base + (uint32_t)(((buf * 128 + row) * 20 + aq * 4) * 4);
        cp_async16(dst, A + (size_t)(m0 + row) * K + k0 + aq * 8);
    }
    // B: 16 k2-rows x 128 words; 16B covers 4 words (4 n)
    int bk = tid >> 5;             // 0..3 (+4*i)
    int bt = tid & 31;             // word group: n = bt*4
    #pragma unroll
    for (int i = 0; i < 4; i++) {
        int krow = bk + 4 * i;
        uint32_t dst = bs_base + (uint32_t)(((buf * 16 + krow) * 136 + bt * 4) * 4);
        cp_async16(dst, Bp + (size_t)(k0 / 2 + krow) * N + n0 + bt * 4);
    }
    cp_commit();
}

__global__ __launch_bounds__(128) void gemm_f16_kernel(
    const __half* __restrict__ A, const uint32_t* __restrict__ Bp,
    const float* __restrict__ bias, const float* __restrict__ res,
    float* __restrict__ C, int M, int N, int K)
{
    __shared__ uint32_t Au[2][128][20];
    __shared__ uint32_t Bu[2][16][136];

    int tid  = threadIdx.x;
    int lane = tid & 31;
    int warp = tid >> 5;
    int wm   = warp >> 1;
    int wn   = warp & 1;
    int r    = lane >> 2;
    int c    = lane & 3;

    int m0 = blockIdx.y * 128;
    int n0 = blockIdx.x * 128;

    uint32_t as_base = (uint32_t)__cvta_generic_to_shared(&Au[0][0][0]);
    uint32_t bs_base = (uint32_t)__cvta_generic_to_shared(&Bu[0][0][0]);

    float acc[4][8][4];
    #pragma unroll
    for (int i = 0; i < 4; i++)
        #pragma unroll
        for (int j = 0; j < 8; j++)
            #pragma unroll
            for (int e = 0; e < 4; e++) acc[i][j][e] = 0.f;

    const int NCHUNK = K / 32;

    gemm_issue_chunk(A, Bp, N, K, m0, n0, tid, as_base, bs_base, 0, 0);

    for (int chunk = 0; chunk < NCHUNK; chunk++) {
        int buf = chunk & 1;
        cp_wait0();
        __syncthreads();

        if (chunk + 1 < NCHUNK)
            gemm_issue_chunk(A, Bp, N, K, m0, n0, tid,
                             as_base, bs_base, chunk + 1, buf ^ 1);

        #pragma unroll
        for (int ks = 0; ks < 2; ks++) {
            int kb = ks * 8;
            uint32_t afrag[4][4];
            #pragma unroll
            for (int i = 0; i < 4; i++) {
                int row = wm * 64 + i * 16 + r;
                afrag[i][0] = Au[buf][row][kb + c];
                afrag[i][1] = Au[buf][row + 8][kb + c];
                afrag[i][2] = Au[buf][row][kb + c + 4];
                afrag[i][3] = Au[buf][row + 8][kb + c + 4];
            }
            uint32_t bfrag[8][2];
            #pragma unroll
            for (int j = 0; j < 8; j++) {
                int col = wn * 64 + j * 8 + r;
                bfrag[j][0] = Bu[buf][kb + c][col];
                bfrag[j][1] = Bu[buf][kb + c + 4][col];
            }
            #pragma unroll
            for (int i = 0; i < 4; i++)
                #pragma unroll
                for (int j = 0; j < 8; j++)
                    mma_f16(acc[i][j], afrag[i], bfrag[j]);
        }
        __syncthreads();
    }

    #pragma unroll
    for (int i = 0; i < 4; i++) {
        int row0 = m0 + wm * 64 + i * 16 + r;
        #pragma unroll
        for (int j = 0; j < 8; j++) {
            int col = n0 + wn * 64 + j * 8 + 2 * c;
            float bv0 = bias[col];
            float bv1 = bias[col + 1];
            size_t idx0 = (size_t)row0 * N + col;
            size_t idx1 = (size_t)(row0 + 8) * N + col;
            float2 o0, o1;
            o0.x = acc[i][j][0] + bv0; o0.y = acc[i][j][1] + bv1;
            o1.x = acc[i][j][2] + bv0; o1.y = acc[i][j][3] + bv1;
            if (res) {
                const float2 r0 = *(const float2*)(res + idx0);
                const float2 r1 = *(const float2*)(res + idx1);
                o0.x += r0.x; o0.y += r0.y;
                o1.x += r1.x; o1.y += r1.y;
            }
            *(float2*)(C + idx0) = o0;
            *(float2*)(C + idx1) = o1;
        }
    }
}

// ---------------------------------------------------------------------------
// Tensor-core attention per (n, h). flat(n,s) = cd*(n/d0) + cm*(n%d0) + cs*s
// tf32 QK + bf16 PV (register-local P handoff). Output written as f16.
// ---------------------------------------------------------------------------
template<int S>
__global__ __launch_bounds__(128) void attn_mma_kernel(
    const float* __restrict__ qkv, __half* __restrict__ att,
    const float* __restrict__ rsin, const float* __restrict__ rcos,
    int d0, int cd, int cm, int cs)
{
    constexpr int NT   = (S + 7) / 8;
    constexpr int QT   = (S + 15) / 16;
    constexpr int KT2  = NT / 2;
    constexpr int NT8  = NT * 8;
    constexpr int KSTR = NT8 + ((8 - (NT8 % 32) + 32) % 32);
    constexpr int QROWS = QT * 16;

    __shared__ float    Qs[QROWS][36];
    __shared__ float    Kt[32][KSTR];
    __shared__ uint32_t Vp[NT * 4][40];

    int n = blockIdx.x;
    int h = blockIdx.y;
    int tid = threadIdx.x;
    int lane = tid & 31;
    int warp = tid >> 5;
    int r = lane >> 2;
    int c = lane & 3;

    int nb = cd * (n / d0) + cm * (n % d0);
    int qoff = h * HD;
    int koff = DD + h * HD;
    int voff = 2 * DD + h * HD;
    const float scale = 0.17677669529663687f;

    for (int idx = tid; idx < QROWS * 32; idx += 128) {
        int j = idx >> 5, d = idx & 31;
        float val = 0.f;
        if (j < S) {
            size_t rowb = (size_t)(nb + cs * j) * (3 * DD);
            if (rsin) {
                int i = d & 15;
                float sn = rsin[j * 16 + i], co = rcos[j * 16 + i];
                float x1 = qkv[rowb + qoff + 2 * i];
                float x2 = qkv[rowb + qoff + 2 * i + 1];
                val = (d < 16) ? (x1 * co - x2 * sn) : (x1 * sn + x2 * co);
            } else {
                val = qkv[rowb + qoff + d];
            }
            val *= scale;
        }
        Qs[j][d] = val;
    }
    for (int idx = tid; idx < NT8 * 32; idx += 128) {
        int j = idx >> 5, d = idx & 31;
        float val = 0.f;
        if (j < S) {
            size_t rowb = (size_t)(nb + cs * j) * (3 * DD);
            if (rsin) {
                int i = d & 15;
                float sn = rsin[j * 16 + i], co = rcos[j * 16 + i];
                float x1 = qkv[rowb + koff + 2 * i];
                float x2 = qkv[rowb + koff + 2 * i + 1];
                val = (d < 16) ? (x1 * co - x2 * sn) : (x1 * sn + x2 * co);
            } else {
                val = qkv[rowb + koff + d];
            }
        }
        Kt[d][j] = val;
    }
    for (int idx = tid; idx < NT * 4 * 32; idx += 128) {
        int j2 = idx >> 5, d = idx & 31;
        int j0 = 2 * j2, j1 = 2 * j2 + 1;
        float v0 = (j0 < S) ? qkv[(size_t)(nb + cs * j0) * (3 * DD) + voff + d] : 0.f;
        float v1 = (j1 < S) ? qkv[(size_t)(nb + cs * j1) * (3 * DD) + voff + d] : 0.f;
        Vp[j2][d] = pack_bf2(v0, v1);
    }
    __syncthreads();

    for (int qt = warp; qt < QT; qt += 4) {
        int q0 = qt * 16;

        uint32_t aq[4][4];
        #pragma unroll
        for (int kb = 0; kb < 4; kb++) {
            aq[kb][0] = __float_as_uint(Qs[q0 + r][kb * 8 + c]);
            aq[kb][1] = __float_as_uint(Qs[q0 + 8 + r][kb * 8 + c]);
            aq[kb][2] = __float_as_uint(Qs[q0 + r][kb * 8 + c + 4]);
            aq[kb][3] = __float_as_uint(Qs[q0 + 8 + r][kb * 8 + c + 4]);
        }

        float sacc[NT][4];
        #pragma unroll
        for (int nt = 0; nt < NT; nt++)
            #pragma unroll
            for (int e = 0; e < 4; e++) sacc[nt][e] = 0.f;

        #pragma unroll
        for (int nt = 0; nt < NT; nt++) {
            #pragma unroll
            for (int kb = 0; kb < 4; kb++) {
                uint32_t bk[2];
                bk[0] = __float_as_uint(Kt[kb * 8 + c][nt * 8 + r]);
                bk[1] = __float_as_uint(Kt[kb * 8 + c + 4][nt * 8 + r]);
                mma_tf32(sacc[nt], aq[kb], bk);
            }
        }

        #pragma unroll
        for (int nt = 0; nt < NT; nt++) {
            int col = nt * 8 + 2 * c;
            if (col >= S)     { sacc[nt][0] = -1e30f; sacc[nt][2] = -1e30f; }
            if (col + 1 >= S) { sacc[nt][1] = -1e30f; sacc[nt][3] = -1e30f; }
        }

        float m0 = -1e30f, m1 = -1e30f;
        #pragma unroll
        for (int nt = 0; nt < NT; nt++) {
            m0 = fmaxf(m0, fmaxf(sacc[nt][0], sacc[nt][1]));
            m1 = fmaxf(m1, fmaxf(sacc[nt][2], sacc[nt][3]));
        }
        m0 = fmaxf(m0, __shfl_xor_sync(0xffffffffu, m0, 1));
        m0 = fmaxf(m0, __shfl_xor_sync(0xffffffffu, m0, 2));
        m1 = fmaxf(m1, __shfl_xor_sync(0xffffffffu, m1, 1));
        m1 = fmaxf(m1, __shfl_xor_sync(0xffffffffu, m1, 2));

        float s0 = 0.f, s1 = 0.f;
        #pragma unroll
        for (int nt = 0; nt < NT; nt++) {
            sacc[nt][0] = __expf(sacc[nt][0] - m0);
            sacc[nt][1] = __expf(sacc[nt][1] - m0);
            sacc[nt][2] = __expf(sacc[nt][2] - m1);
            sacc[nt][3] = __expf(sacc[nt][3] - m1);
            s0 += sacc[nt][0] + sacc[nt][1];
            s1 += sacc[nt][2] + sacc[nt][3];
        }
        s0 += __shfl_xor_sync(0xffffffffu, s0, 1);
        s0 += __shfl_xor_sync(0xffffffffu, s0, 2);
        s1 += __shfl_xor_sync(0xffffffffu, s1, 1);
        s1 += __shfl_xor_sync(0xffffffffu, s1, 2);
        float rinv0 = 1.f / s0;
        float rinv1 = 1.f / s1;

        uint32_t pa[KT2][4];
        #pragma unroll
        for (int kt = 0; kt < KT2; kt++) {
            int nt0 = 2 * kt, nt1 = 2 * kt + 1;
            pa[kt][0] = pack_bf2(sacc[nt0][0], sacc[nt0][1]);
            pa[kt][1] = pack_bf2(sacc[nt0][2], sacc[nt0][3]);
            pa[kt][2] = pack_bf2(sacc[nt1][0], sacc[nt1][1]);
            pa[kt][3] = pack_bf2(sacc[nt1][2], sacc[nt1][3]);
        }

        float oacc[4][4];
        #pragma unroll
        for (int dt = 0; dt < 4; dt++)
            #pragma unroll
            for (int e = 0; e < 4; e++) oacc[dt][e] = 0.f;

        #pragma unroll
        for (int kt = 0; kt < KT2; kt++) {
            #pragma unroll
            for (int dt = 0; dt < 4; dt++) {
                uint32_t bv[2];
                bv[0] = Vp[8 * kt + c][dt * 8 + r];
                bv[1] = Vp[8 * kt + c + 4][dt * 8 + r];
                mma_bf16(oacc[dt], pa[kt], bv);
            }
        }

        int row0 = q0 + r;
        int row1 = q0 + 8 + r;
        #pragma unroll
        for (int dt = 0; dt < 4; dt++) {
            if (row0 < S) {
                uint32_t o = pack_h2(oacc[dt][0] * rinv0, oacc[dt][1] * rinv0);
                *(uint32_t*)&att[(size_t)(nb + cs * row0) * DD + h * HD + dt * 8 + 2 * c] = o;
            }
            if (row1 < S) {
                uint32_t o = pack_h2(oacc[dt][2] * rinv1, oacc[dt][3] * rinv1);
                *(uint32_t*)&att[(size_t)(nb + cs * row1) * DD + h * HD + dt * 8 + 2 * c] = o;
            }
        }
    }
}

// ---------------------------------------------------------------------------
// Host launcher
// ---------------------------------------------------------------------------
extern "C" void kernel_launch(void* const* d_in, const int* in_sizes, int n_in,
                              void* d_out, int out_size)
{
    const float* x         = (const float*)d_in[0];
    const float* lat_grid  = (const float*)d_in[1];
    const float* lon_grid  = (const float*)d_in[2];
    const float* lat_qkv_w = (const float*)d_in[3];
    const float* lat_qkv_b = (const float*)d_in[4];
    const float* lon_qkv_w = (const float*)d_in[5];
    const float* lon_qkv_b = (const float*)d_in[6];
    const float* lev_qkv_w = (const float*)d_in[7];
    const float* lev_qkv_b = (const float*)d_in[8];
    const float* proj_w    = (const float*)d_in[9];
    const float* proj_b    = (const float*)d_in[10];
    const float* g_lat     = (const float*)d_in[11];
    const float* b_lat     = (const float*)d_in[12];
    const float* g_lon     = (const float*)d_in[13];
    const float* b_lon     = (const float*)d_in[14];
    const float* g_lev     = (const float*)d_in[15];
    const float* b_lev     = (const float*)d_in[16];
    float* out = (float*)d_out;

    __half *lnh, *atth;
    float *qkv, *state, *slat, *clat, *slon, *clon;
    uint32_t *wpq, *wpp;
    cudaGetSymbolAddress((void**)&lnh,   g_lnh);
    cudaGetSymbolAddress((void**)&qkv,   g_qkv);
    cudaGetSymbolAddress((void**)&atth,  g_atth);
    cudaGetSymbolAddress((void**)&state, g_state);
    cudaGetSymbolAddress((void**)&slat,  g_sin_lat);
    cudaGetSymbolAddress((void**)&clat,  g_cos_lat);
    cudaGetSymbolAddress((void**)&slon,  g_sin_lon);
    cudaGetSymbolAddress((void**)&clon,  g_cos_lon);
    cudaGetSymbolAddress((void**)&wpq,   g_wp_qkv);
    cudaGetSymbolAddress((void**)&wpp,   g_wp_proj);

    uint32_t* wp_lat = wpq;
    uint32_t* wp_lon = wpq + (size_t)(DD / 2) * 3 * DD;
    uint32_t* wp_lev = wpq + (size_t)2 * (DD / 2) * 3 * DD;

    // Pack weights to f16-pair words
    pack_w_kernel<<<dim3(3 * DD / 256, DD / 2), 256>>>(lat_qkv_w, wp_lat, DD, 3 * DD);
    pack_w_kernel<<<dim3(3 * DD / 256, DD / 2), 256>>>(lon_qkv_w, wp_lon, DD, 3 * DD);
    pack_w_kernel<<<dim3(3 * DD / 256, DD / 2), 256>>>(lev_qkv_w, wp_lev, DD, 3 * DD);
    pack_w_kernel<<<dim3(DD / 256, DD / 2), 256>>>(proj_w, wpp, DD, DD);

    rotary_kernel<<<(HH * 16 + 127) / 128, 128>>>(lat_grid, HH, 0, slat, clat);
    rotary_kernel<<<(WW * 16 + 127) / 128, 128>>>(lon_grid, WW, 1, slon, clon);

    dim3 gq(3 * DD / 128, TT / 128);   // (12, 468)
    dim3 gp(DD / 128, TT / 128);       // (4, 468)

    // ---- lat block (seq = H, n over (l,w)) ----
    ln_kernel<<<TT, 128>>>(x, g_lat, b_lat, lnh);
    gemm_f16_kernel<<<gq, 128>>>(lnh, wp_lat, lat_qkv_b, nullptr, qkv, TT, 3 * DD, DD);
    attn_mma_kernel<HH><<<dim3(LL * WW, NHEAD), 128>>>(qkv, atth, slat, clat,
                                                       WW, HH * WW, 1, WW);
    gemm_f16_kernel<<<gp, 128>>>(atth, wpp, proj_b, x, state, TT, DD, DD);

    // ---- lon block (seq = W, n over (l,h)) ----
    ln_kernel<<<TT, 128>>>(state, g_lon, b_lon, lnh);
    gemm_f16_kernel<<<gq, 128>>>(lnh, wp_lon, lon_qkv_b, nullptr, qkv, TT, 3 * DD, DD);
    attn_mma_kernel<WW><<<dim3(LL * HH, NHEAD), 128>>>(qkv, atth, slon, clon,
                                                       1, WW, 0, 1);
    gemm_f16_kernel<<<gp, 128>>>(atth, wpp, proj_b, state, state, TT, DD, DD);

    // ---- lev block (seq = L, n over (h,w), no rotary) ----
    ln_kernel<<<TT, 128>>>(state, g_lev, b_lev, lnh);
    gemm_f16_kernel<<<gq, 128>>>(lnh, wp_lev, lev_qkv_b, nullptr, qkv, TT, 3 * DD, DD);
    attn_mma_kernel<LL><<<dim3(HH * WW, NHEAD), 128>>>(qkv, atth, nullptr, nullptr,
                                                       1, 1, 0, HH * WW);
    gemm_f16_kernel<<<gp, 128>>>(atth, wpp, proj_b, state, out, TT, DD, DD);
}